// round 1
// baseline (speedup 1.0000x reference)
#include <cuda_runtime.h>

#define BATCH 128
#define TFRM 80
#define DECL 30
#define DSTEPS 29
#define EDIM 512
#define G4 2048
#define FEATD 4096
#define VOC 6000
#define NSPLIT 8

// ---------------- scratch (static device globals; no allocation) ----------------
__device__ float g_X1pre[TFRM * BATCH * G4];      // encoder input gates (incl bias1)
__device__ float g_Wx2[DSTEPS * BATCH * G4];      // decoder word-input gates (no bias)
__device__ float g_W2cat[G4 * 1024];              // [w_ih2[:,E:2E] ; w_hh2] fused, ld=1024
__device__ float g_bias1[G4];
__device__ float g_bias2[G4];
__device__ float g_h12[BATCH * 1024];             // [h1 | h2] per row
__device__ float g_c1[BATCH * EDIM];
__device__ float g_c2[BATCH * EDIM];
__device__ float g_part[NSPLIT * BATCH * G4];     // split-K partials
__device__ float g_H2[DSTEPS * BATCH * EDIM];     // decoder h2 history
__device__ float g_logits[DSTEPS * BATCH * VOC];
__device__ int   g_labels[DSTEPS * BATCH];
__device__ float g_rowloss[DSTEPS * BATCH];

// ---------------- helpers ----------------
union F2U { float2 f; unsigned long long u; };

__device__ __forceinline__ unsigned long long fma2(unsigned long long a,
                                                   unsigned long long b,
                                                   unsigned long long c) {
    asm("fma.rn.f32x2 %0, %1, %2, %0;" : "+l"(c) : "l"(a), "l"(b));
    return c;
}

__device__ __forceinline__ float sigmoidf_(float x) {
    return 1.0f / (1.0f + expf(-x));
}

// ---------------- init: zero state, combine biases, init out ----------------
__global__ void init_kernel(const float* __restrict__ b_ih1, const float* __restrict__ b_hh1,
                            const float* __restrict__ b_ih2, const float* __restrict__ b_hh2,
                            float* out) {
    int idx = blockIdx.x * blockDim.x + threadIdx.x;  // 0 .. 262143
    if (idx < BATCH * 1024) g_h12[idx] = 0.0f;
    else if (idx < BATCH * 1024 + BATCH * EDIM) g_c1[idx - BATCH * 1024] = 0.0f;
    else g_c2[idx - (BATCH * 1024 + BATCH * EDIM)] = 0.0f;
    if (idx < G4) {
        g_bias1[idx] = b_ih1[idx] + b_hh1[idx];
        g_bias2[idx] = b_ih2[idx] + b_hh2[idx];
    }
    if (idx == 0) out[0] = 0.0f;
}

// ---------------- fuse cell2 weights: [w_ih2[:,512:1024] ; w_hh2] ----------------
__global__ void w2cat_kernel(const float* __restrict__ w_ih2, const float* __restrict__ w_hh2) {
    int idx = blockIdx.x * blockDim.x + threadIdx.x;  // 2048*1024
    int n = idx >> 10, k = idx & 1023;
    g_W2cat[idx] = (k < EDIM) ? w_ih2[n * 1024 + EDIM + k] : w_hh2[n * EDIM + (k - EDIM)];
}

// ---------------- generic tiled SGEMM with f32x2 packed FMA ----------------
// C[M,N] = A @ W^T (+bias), A row m (m = by*128 + mi) at A + by*sT + mi*sB,
// W[n,k] = W[n*ldW + k]. If gridDim.z>1: block z computes K chunk [z*kChunk, ...)
// and writes partials at C + z*M*N (no bias).
__global__ __launch_bounds__(256, 1)
void sgemm_kernel(const float* __restrict__ A, size_t sT, size_t sB,
                  const float* __restrict__ W, int ldW,
                  const float* __restrict__ bias,
                  float* __restrict__ C, int N, int kChunk, int Mtot) {
    __shared__ unsigned long long As2[16][128];  // duplicated (a,a) pairs
    __shared__ float Ws[16][128];

    const int tid = threadIdx.x;
    const int bx = blockIdx.x, by = blockIdx.y, bz = blockIdx.z;
    const float* Ab = A + (size_t)by * sT;
    const int n0 = bx * 128;
    const int k0 = bz * kChunk;
    const int tx = tid & 15, ty = tid >> 4;

    unsigned long long acc[8][4];
#pragma unroll
    for (int i = 0; i < 8; i++)
#pragma unroll
        for (int j = 0; j < 4; j++) acc[i][j] = 0ull;

    for (int kt = 0; kt < kChunk; kt += 16) {
        // load A tile (128 rows x 16 k) as float4 along k, store duplicated pairs
#pragma unroll
        for (int l = 0; l < 2; l++) {
            int f4 = tid * 2 + l;          // 0..511
            int mi = f4 >> 2;
            int k4 = (f4 & 3) * 4;
            float4 v = *(const float4*)(Ab + (size_t)mi * sB + (size_t)(k0 + kt + k4));
            F2U u;
            u.f = make_float2(v.x, v.x); As2[k4 + 0][mi] = u.u;
            u.f = make_float2(v.y, v.y); As2[k4 + 1][mi] = u.u;
            u.f = make_float2(v.z, v.z); As2[k4 + 2][mi] = u.u;
            u.f = make_float2(v.w, v.w); As2[k4 + 3][mi] = u.u;
        }
        // load W tile (128 n x 16 k), guard n edge (N=6000 case)
#pragma unroll
        for (int l = 0; l < 2; l++) {
            int f4 = tid * 2 + l;
            int ni = f4 >> 2;
            int k4 = (f4 & 3) * 4;
            int gn = n0 + ni;
            float4 v = make_float4(0.f, 0.f, 0.f, 0.f);
            if (gn < N) v = *(const float4*)(W + (size_t)gn * ldW + (size_t)(k0 + kt + k4));
            Ws[k4 + 0][ni] = v.x;
            Ws[k4 + 1][ni] = v.y;
            Ws[k4 + 2][ni] = v.z;
            Ws[k4 + 3][ni] = v.w;
        }
        __syncthreads();
#pragma unroll
        for (int k = 0; k < 16; k++) {
            unsigned long long a2[8];
            F2U b2[4];
#pragma unroll
            for (int i = 0; i < 8; i++) a2[i] = As2[k][ty * 8 + i];
            const float2* wrow = (const float2*)(&Ws[k][0]);
#pragma unroll
            for (int j = 0; j < 4; j++) b2[j].f = wrow[tx * 4 + j];
#pragma unroll
            for (int i = 0; i < 8; i++)
#pragma unroll
                for (int j = 0; j < 4; j++) acc[i][j] = fma2(a2[i], b2[j].u, acc[i][j]);
        }
        __syncthreads();
    }

    const bool split = (gridDim.z > 1);
    float* Cb = split ? (C + (size_t)bz * (size_t)Mtot * (size_t)N) : C;
#pragma unroll
    for (int i = 0; i < 8; i++) {
        size_t gm = (size_t)by * 128 + ty * 8 + i;
#pragma unroll
        for (int j = 0; j < 4; j++) {
            F2U u; u.u = acc[i][j];
            int gn = n0 + tx * 8 + 2 * j;
            if (gn < N) {
                float b0 = (!split && bias) ? bias[gn] : 0.0f;
                Cb[gm * N + gn] = u.f.x + b0;
            }
            if (gn + 1 < N) {
                float b1 = (!split && bias) ? bias[gn + 1] : 0.0f;
                Cb[gm * N + gn + 1] = u.f.y + b1;
            }
        }
    }
}

// ---------------- LSTM pointwise: sum split-K partials + xpre + bias, gates ----------------
__global__ void cell_pointwise(const float* __restrict__ xpre,   // [128,2048] or null
                               const float* __restrict__ bias,   // [2048] or null
                               float* __restrict__ c,            // [128,512]
                               float* __restrict__ h12,          // [128,1024]
                               int hoff,                         // 0 (h1) or 512 (h2)
                               float* __restrict__ hcopy) {      // null or H2 slot
    int idx = blockIdx.x * blockDim.x + threadIdx.x;  // 65536
    int b = idx >> 9, j = idx & 511;
    float gi = 0.f, gf = 0.f, gg = 0.f, go = 0.f;
#pragma unroll
    for (int s = 0; s < NSPLIT; s++) {
        const float* p = g_part + (size_t)s * (BATCH * G4) + (size_t)b * G4;
        gi += p[j]; gf += p[EDIM + j]; gg += p[1024 + j]; go += p[1536 + j];
    }
    if (xpre) {
        const float* x = xpre + (size_t)b * G4;
        gi += x[j]; gf += x[EDIM + j]; gg += x[1024 + j]; go += x[1536 + j];
    }
    if (bias) {
        gi += bias[j]; gf += bias[EDIM + j]; gg += bias[1024 + j]; go += bias[1536 + j];
    }
    float iv = sigmoidf_(gi);
    float fv = sigmoidf_(gf);
    float gv = tanhf(gg);
    float ov = sigmoidf_(go);
    float cnew = fv * c[idx] + iv * gv;
    c[idx] = cnew;
    float h = ov * tanhf(cnew);
    h12[b * 1024 + hoff + j] = h;
    if (hcopy) hcopy[idx] = h;
}

// ---------------- argmax over vocab (first occurrence, like jnp.argmax) ----------------
__global__ void argmax_kernel(const float* __restrict__ oh) {
    int r = blockIdx.x;           // r = s*128 + b, s in [0,29)
    int s = r >> 7, b = r & 127;
    const float* row = oh + (size_t)b * (DECL * VOC) + (size_t)(s + 1) * VOC;
    __shared__ float sv[128];
    __shared__ int si[128];
    int tid = threadIdx.x;
    float best = -3.4e38f; int bi = 0;
    for (int i = tid; i < VOC; i += 128) {
        float v = row[i];
        if (v > best) { best = v; bi = i; }
    }
    sv[tid] = best; si[tid] = bi;
    __syncthreads();
    for (int o = 64; o > 0; o >>= 1) {
        if (tid < o) {
            if (sv[tid + o] > sv[tid] || (sv[tid + o] == sv[tid] && si[tid + o] < si[tid])) {
                sv[tid] = sv[tid + o]; si[tid] = si[tid + o];
            }
        }
        __syncthreads();
    }
    if (tid == 0) g_labels[r] = si[0];
}

// ---------------- per-row NLL from logits ----------------
__global__ void loss_kernel() {
    int r = blockIdx.x;  // 3712
    const float* row = g_logits + (size_t)r * VOC;
    __shared__ float red[256];
    int tid = threadIdx.x;
    float m = -3.4e38f;
    for (int i = tid; i < VOC; i += 256) m = fmaxf(m, row[i]);
    red[tid] = m; __syncthreads();
    for (int o = 128; o > 0; o >>= 1) {
        if (tid < o) red[tid] = fmaxf(red[tid], red[tid + o]);
        __syncthreads();
    }
    float mall = red[0];
    __syncthreads();
    float sacc = 0.f;
    for (int i = tid; i < VOC; i += 256) sacc += expf(row[i] - mall);
    red[tid] = sacc; __syncthreads();
    for (int o = 128; o > 0; o >>= 1) {
        if (tid < o) red[tid] += red[tid + o];
        __syncthreads();
    }
    if (tid == 0) {
        int lab = g_labels[r];
        g_rowloss[r] = (mall + logf(red[0])) - row[lab];
    }
}

__global__ void final_reduce(float* out) {
    __shared__ float red[256];
    int tid = threadIdx.x;
    float s = 0.f;
    for (int i = tid; i < DSTEPS * BATCH; i += 256) s += g_rowloss[i];
    red[tid] = s; __syncthreads();
    for (int o = 128; o > 0; o >>= 1) {
        if (tid < o) red[tid] += red[tid + o];
        __syncthreads();
    }
    if (tid == 0) out[0] = red[0] * (1.0f / 128.0f);
}

// ---------------- host ----------------
extern "C" void kernel_launch(void* const* d_in, const int* in_sizes, int n_in,
                              void* d_out, int out_size) {
    const float* feat    = (const float*)d_in[0];
    const float* caption = (const float*)d_in[1];
    const float* oh      = (const float*)d_in[2];
    const float* w_ih1   = (const float*)d_in[3];
    const float* w_hh1   = (const float*)d_in[4];
    const float* b_ih1   = (const float*)d_in[5];
    const float* b_hh1   = (const float*)d_in[6];
    const float* w_ih2   = (const float*)d_in[7];
    const float* w_hh2   = (const float*)d_in[8];
    const float* b_ih2   = (const float*)d_in[9];
    const float* b_hh2   = (const float*)d_in[10];
    const float* w_out   = (const float*)d_in[11];
    const float* b_out   = (const float*)d_in[12];
    float* out = (float*)d_out;

    float *pX1, *pWx2, *pW2, *pB1, *pB2, *pH12, *pC1, *pC2, *pPart, *pH2, *pLog;
    cudaGetSymbolAddress((void**)&pX1,  g_X1pre);
    cudaGetSymbolAddress((void**)&pWx2, g_Wx2);
    cudaGetSymbolAddress((void**)&pW2,  g_W2cat);
    cudaGetSymbolAddress((void**)&pB1,  g_bias1);
    cudaGetSymbolAddress((void**)&pB2,  g_bias2);
    cudaGetSymbolAddress((void**)&pH12, g_h12);
    cudaGetSymbolAddress((void**)&pC1,  g_c1);
    cudaGetSymbolAddress((void**)&pC2,  g_c2);
    cudaGetSymbolAddress((void**)&pPart, g_part);
    cudaGetSymbolAddress((void**)&pH2,  g_H2);
    cudaGetSymbolAddress((void**)&pLog, g_logits);

    init_kernel<<<1024, 256>>>(b_ih1, b_hh1, b_ih2, b_hh2, out);
    w2cat_kernel<<<8192, 256>>>(w_ih2, w_hh2);

    // X1pre[t,b,:] = feat[b,t,:] @ w_ih1^T + (b_ih1 + b_hh1)
    sgemm_kernel<<<dim3(16, 80, 1), 256>>>(feat, (size_t)FEATD, (size_t)TFRM * FEATD,
                                           w_ih1, FEATD, pB1, pX1, G4, FEATD, TFRM * BATCH);
    // Wx2[s,b,:] = caption[b,s,:] @ w_ih2[:, :512]^T   (no bias)
    sgemm_kernel<<<dim3(16, 29, 1), 256>>>(caption, (size_t)EDIM, (size_t)DECL * EDIM,
                                           w_ih2, 1024, nullptr, pWx2, G4, EDIM, DSTEPS * BATCH);
    argmax_kernel<<<DSTEPS * BATCH, 128>>>(oh);

    // encoder: 80 steps
    for (int t = 0; t < TFRM; t++) {
        sgemm_kernel<<<dim3(16, 1, NSPLIT), 256>>>(pH12, 0, 1024, w_hh1, EDIM, nullptr,
                                                   pPart, G4, EDIM / NSPLIT, BATCH);
        cell_pointwise<<<256, 256>>>(pX1 + (size_t)t * BATCH * G4, nullptr, pC1, pH12, 0, nullptr);
        sgemm_kernel<<<dim3(16, 1, NSPLIT), 256>>>(pH12, 0, 1024, pW2, 1024, nullptr,
                                                   pPart, G4, 1024 / NSPLIT, BATCH);
        cell_pointwise<<<256, 256>>>(nullptr, pB2, pC2, pH12, 512, nullptr);
    }
    // decoder: 29 steps
    for (int s = 0; s < DSTEPS; s++) {
        sgemm_kernel<<<dim3(16, 1, NSPLIT), 256>>>(pH12, 0, 1024, w_hh1, EDIM, nullptr,
                                                   pPart, G4, EDIM / NSPLIT, BATCH);
        cell_pointwise<<<256, 256>>>(nullptr, pB1, pC1, pH12, 0, nullptr);
        sgemm_kernel<<<dim3(16, 1, NSPLIT), 256>>>(pH12, 0, 1024, pW2, 1024, nullptr,
                                                   pPart, G4, 1024 / NSPLIT, BATCH);
        cell_pointwise<<<256, 256>>>(pWx2 + (size_t)s * BATCH * G4, pB2, pC2, pH12, 512,
                                     pH2 + (size_t)s * BATCH * EDIM);
    }

    // logits = H2 @ w_out^T + b_out  -> [3712, 6000]
    sgemm_kernel<<<dim3(47, 29, 1), 256>>>(pH2, (size_t)BATCH * EDIM, (size_t)EDIM,
                                           w_out, EDIM, b_out, pLog, VOC, EDIM, DSTEPS * BATCH);
    loss_kernel<<<DSTEPS * BATCH, 256>>>();
    final_reduce<<<1, 256>>>(out);
}

// round 2
// speedup vs baseline: 2.9903x; 2.9903x over previous
#include <cuda_runtime.h>
#include <stdint.h>

#define BATCH 128
#define TFRM 80
#define DECL 30
#define DSTEPS 29
#define EDIM 512
#define G4 2048
#define FEATD 4096
#define VOC 6000
#define NSPLIT 8

// ---------------- scratch (static device globals; no allocation) ----------------
__device__ float g_X1pre[TFRM * BATCH * G4];      // encoder input gates (incl bias1)
__device__ float g_Wx2[DSTEPS * BATCH * G4];      // decoder word-input gates (no bias)
__device__ float g_W2cat[G4 * 1024];              // [w_ih2[:,E:2E] ; w_hh2] fused, ld=1024
__device__ float g_bias1[G4];
__device__ float g_bias2[G4];
__device__ float g_h12[BATCH * 1024];             // [h1 | h2] per row
__device__ float g_c1[BATCH * EDIM];
__device__ float g_c2[BATCH * EDIM];
__device__ float g_part[NSPLIT * BATCH * G4];     // split-K partials
__device__ float g_H2[DSTEPS * BATCH * EDIM];     // decoder h2 history
__device__ float g_logits[DSTEPS * BATCH * VOC];
__device__ int   g_labels[DSTEPS * BATCH];
__device__ float g_rowloss[DSTEPS * BATCH];

__device__ __forceinline__ float sigmoidf_(float x) {
    return 1.0f / (1.0f + expf(-x));
}

__device__ __forceinline__ uint32_t f2tf32(float x) {
    uint32_t u;
    asm("cvt.rna.tf32.f32 %0, %1;" : "=r"(u) : "f"(x));
    return u;
}

__device__ __forceinline__ void mma_tf32(float* d, const uint32_t* a, const uint32_t* b) {
    asm volatile(
        "mma.sync.aligned.m16n8k8.row.col.f32.tf32.tf32.f32 "
        "{%0,%1,%2,%3}, {%4,%5,%6,%7}, {%8,%9}, {%0,%1,%2,%3};"
        : "+f"(d[0]), "+f"(d[1]), "+f"(d[2]), "+f"(d[3])
        : "r"(a[0]), "r"(a[1]), "r"(a[2]), "r"(a[3]), "r"(b[0]), "r"(b[1]));
}

// ---------------- init: zero state, combine biases, init out ----------------
__global__ void init_kernel(const float* __restrict__ b_ih1, const float* __restrict__ b_hh1,
                            const float* __restrict__ b_ih2, const float* __restrict__ b_hh2,
                            float* out) {
    int idx = blockIdx.x * blockDim.x + threadIdx.x;  // 0 .. 262143
    if (idx < BATCH * 1024) g_h12[idx] = 0.0f;
    else if (idx < BATCH * 1024 + BATCH * EDIM) g_c1[idx - BATCH * 1024] = 0.0f;
    else g_c2[idx - (BATCH * 1024 + BATCH * EDIM)] = 0.0f;
    if (idx < G4) {
        g_bias1[idx] = b_ih1[idx] + b_hh1[idx];
        g_bias2[idx] = b_ih2[idx] + b_hh2[idx];
    }
    if (idx == 0) out[0] = 0.0f;
}

// ---------------- fuse cell2 weights: [w_ih2[:,512:1024] ; w_hh2] ----------------
__global__ void w2cat_kernel(const float* __restrict__ w_ih2, const float* __restrict__ w_hh2) {
    int idx = blockIdx.x * blockDim.x + threadIdx.x;  // 2048*1024
    int n = idx >> 10, k = idx & 1023;
    g_W2cat[idx] = (k < EDIM) ? w_ih2[n * 1024 + EDIM + k] : w_hh2[n * EDIM + (k - EDIM)];
}

// ---------------- tf32 tensor-core GEMM: C[M,N] = A @ W^T (+bias) ----------------
// Tile 128x128, BK=32, 256 threads (8 warps as 2m x 4n, each warp 64m x 32n).
// A row m (m = by*128 + mi) at A + by*sT + mi*sB. W[n,k] at W + n*ldW + k.
// If gridDim.z > 1: block z computes K range [z*kChunk, (z+1)*kChunk), writes
// partials at C + z*Mtot*N (no bias).
#define SMP 36   // smem pitch in floats (conflict-free fragment loads)

__global__ __launch_bounds__(256, 2)
void mma_gemm(const float* __restrict__ A, size_t sT, size_t sB,
              const float* __restrict__ W, int ldW,
              const float* __restrict__ bias,
              float* __restrict__ C, int N, int kChunk, int Mtot) {
    __shared__ uint32_t As[128 * SMP];
    __shared__ uint32_t Bs[128 * SMP];

    const int tid = threadIdx.x;
    const int lane = tid & 31;
    const int wid = tid >> 5;
    const int g = lane >> 2;        // groupID 0..7
    const int t = lane & 3;         // thread-in-group 0..3
    const int warpM = wid >> 2;     // 0..1 -> 64 rows
    const int warpN = wid & 3;      // 0..3 -> 32 cols

    const int bx = blockIdx.x, by = blockIdx.y, bz = blockIdx.z;
    const float* Ab = A + (size_t)by * sT;
    const int n0 = bx * 128;
    const int k0 = bz * kChunk;

    float acc[4][4][4];
#pragma unroll
    for (int i = 0; i < 4; i++)
#pragma unroll
        for (int j = 0; j < 4; j++)
#pragma unroll
            for (int r = 0; r < 4; r++) acc[i][j][r] = 0.0f;

    for (int kt = 0; kt < kChunk; kt += 32) {
        // ---- load A tile: 128 rows x 32 k (coalesced float4 along k) ----
#pragma unroll
        for (int it = 0; it < 4; it++) {
            int f4 = it * 256 + tid;      // 0..1023
            int m  = f4 >> 3;             // 0..127
            int k4 = (f4 & 7) * 4;
            float4 v = *(const float4*)(Ab + (size_t)m * sB + (size_t)(k0 + kt + k4));
            As[m * SMP + k4 + 0] = f2tf32(v.x);
            As[m * SMP + k4 + 1] = f2tf32(v.y);
            As[m * SMP + k4 + 2] = f2tf32(v.z);
            As[m * SMP + k4 + 3] = f2tf32(v.w);
        }
        // ---- load W tile: 128 n x 32 k, guard n edge ----
#pragma unroll
        for (int it = 0; it < 4; it++) {
            int f4 = it * 256 + tid;
            int n  = f4 >> 3;
            int k4 = (f4 & 7) * 4;
            int gn = n0 + n;
            float4 v = make_float4(0.f, 0.f, 0.f, 0.f);
            if (gn < N) v = *(const float4*)(W + (size_t)gn * ldW + (size_t)(k0 + kt + k4));
            Bs[n * SMP + k4 + 0] = f2tf32(v.x);
            Bs[n * SMP + k4 + 1] = f2tf32(v.y);
            Bs[n * SMP + k4 + 2] = f2tf32(v.z);
            Bs[n * SMP + k4 + 3] = f2tf32(v.w);
        }
        __syncthreads();

#pragma unroll
        for (int ks = 0; ks < 4; ks++) {
            const int kb = ks * 8;
            uint32_t afr[4][4];
#pragma unroll
            for (int mt = 0; mt < 4; mt++) {
                int row = warpM * 64 + mt * 16;
                afr[mt][0] = As[(row + g) * SMP + kb + t];
                afr[mt][1] = As[(row + g + 8) * SMP + kb + t];
                afr[mt][2] = As[(row + g) * SMP + kb + t + 4];
                afr[mt][3] = As[(row + g + 8) * SMP + kb + t + 4];
            }
            uint32_t bfr[4][2];
#pragma unroll
            for (int nt = 0; nt < 4; nt++) {
                int col = warpN * 32 + nt * 8;
                bfr[nt][0] = Bs[(col + g) * SMP + kb + t];
                bfr[nt][1] = Bs[(col + g) * SMP + kb + t + 4];
            }
#pragma unroll
            for (int mt = 0; mt < 4; mt++)
#pragma unroll
                for (int nt = 0; nt < 4; nt++)
                    mma_tf32(acc[mt][nt], afr[mt], bfr[nt]);
        }
        __syncthreads();
    }

    const bool split = (gridDim.z > 1);
    float* Cb = split ? (C + (size_t)bz * (size_t)Mtot * (size_t)N) : C;

#pragma unroll
    for (int mt = 0; mt < 4; mt++) {
        size_t gm0 = (size_t)by * 128 + warpM * 64 + mt * 16 + g;
#pragma unroll
        for (int nt = 0; nt < 4; nt++) {
            int gc = n0 + warpN * 32 + nt * 8 + 2 * t;
#pragma unroll
            for (int r = 0; r < 4; r++) {
                size_t gm = gm0 + (r >= 2 ? 8 : 0);
                int cc = gc + (r & 1);
                if (cc < N) {
                    float b0 = (!split && bias) ? bias[cc] : 0.0f;
                    Cb[gm * N + cc] = acc[mt][nt][r] + b0;
                }
            }
        }
    }
}

// ---------------- LSTM pointwise: sum split-K partials + xpre + bias, gates ----------------
__global__ void cell_pointwise(const float* __restrict__ xpre,   // [128,2048] or null
                               const float* __restrict__ bias,   // [2048] or null
                               float* __restrict__ c,            // [128,512]
                               float* __restrict__ h12,          // [128,1024]
                               int hoff,                         // 0 (h1) or 512 (h2)
                               float* __restrict__ hcopy) {      // null or H2 slot
    int idx = blockIdx.x * blockDim.x + threadIdx.x;  // 65536
    int b = idx >> 9, j = idx & 511;
    float gi = 0.f, gf = 0.f, gg = 0.f, go = 0.f;
#pragma unroll
    for (int s = 0; s < NSPLIT; s++) {
        const float* p = g_part + (size_t)s * (BATCH * G4) + (size_t)b * G4;
        gi += p[j]; gf += p[EDIM + j]; gg += p[1024 + j]; go += p[1536 + j];
    }
    if (xpre) {
        const float* x = xpre + (size_t)b * G4;
        gi += x[j]; gf += x[EDIM + j]; gg += x[1024 + j]; go += x[1536 + j];
    }
    if (bias) {
        gi += bias[j]; gf += bias[EDIM + j]; gg += bias[1024 + j]; go += bias[1536 + j];
    }
    float iv = sigmoidf_(gi);
    float fv = sigmoidf_(gf);
    float gv = tanhf(gg);
    float ov = sigmoidf_(go);
    float cnew = fv * c[idx] + iv * gv;
    c[idx] = cnew;
    float h = ov * tanhf(cnew);
    h12[b * 1024 + hoff + j] = h;
    if (hcopy) hcopy[idx] = h;
}

// ---------------- argmax over vocab (first occurrence, like jnp.argmax) ----------------
__global__ void argmax_kernel(const float* __restrict__ oh) {
    int r = blockIdx.x;           // r = s*128 + b, s in [0,29)
    int s = r >> 7, b = r & 127;
    const float* row = oh + (size_t)b * (DECL * VOC) + (size_t)(s + 1) * VOC;
    __shared__ float sv[128];
    __shared__ int si[128];
    int tid = threadIdx.x;
    float best = -3.4e38f; int bi = 0;
    for (int i = tid; i < VOC; i += 128) {
        float v = row[i];
        if (v > best) { best = v; bi = i; }
    }
    sv[tid] = best; si[tid] = bi;
    __syncthreads();
    for (int o = 64; o > 0; o >>= 1) {
        if (tid < o) {
            if (sv[tid + o] > sv[tid] || (sv[tid + o] == sv[tid] && si[tid + o] < si[tid])) {
                sv[tid] = sv[tid + o]; si[tid] = si[tid + o];
            }
        }
        __syncthreads();
    }
    if (tid == 0) g_labels[r] = si[0];
}

// ---------------- per-row NLL from logits ----------------
__global__ void loss_kernel() {
    int r = blockIdx.x;  // 3712
    const float* row = g_logits + (size_t)r * VOC;
    __shared__ float red[256];
    int tid = threadIdx.x;
    float m = -3.4e38f;
    for (int i = tid; i < VOC; i += 256) m = fmaxf(m, row[i]);
    red[tid] = m; __syncthreads();
    for (int o = 128; o > 0; o >>= 1) {
        if (tid < o) red[tid] = fmaxf(red[tid], red[tid + o]);
        __syncthreads();
    }
    float mall = red[0];
    __syncthreads();
    float sacc = 0.f;
    for (int i = tid; i < VOC; i += 256) sacc += expf(row[i] - mall);
    red[tid] = sacc; __syncthreads();
    for (int o = 128; o > 0; o >>= 1) {
        if (tid < o) red[tid] += red[tid + o];
        __syncthreads();
    }
    if (tid == 0) {
        int lab = g_labels[r];
        g_rowloss[r] = (mall + logf(red[0])) - row[lab];
    }
}

__global__ void final_reduce(float* out) {
    __shared__ float red[256];
    int tid = threadIdx.x;
    float s = 0.f;
    for (int i = tid; i < DSTEPS * BATCH; i += 256) s += g_rowloss[i];
    red[tid] = s; __syncthreads();
    for (int o = 128; o > 0; o >>= 1) {
        if (tid < o) red[tid] += red[tid + o];
        __syncthreads();
    }
    if (tid == 0) out[0] = red[0] * (1.0f / 128.0f);
}

// ---------------- host ----------------
extern "C" void kernel_launch(void* const* d_in, const int* in_sizes, int n_in,
                              void* d_out, int out_size) {
    const float* feat    = (const float*)d_in[0];
    const float* caption = (const float*)d_in[1];
    const float* oh      = (const float*)d_in[2];
    const float* w_ih1   = (const float*)d_in[3];
    const float* w_hh1   = (const float*)d_in[4];
    const float* b_ih1   = (const float*)d_in[5];
    const float* b_hh1   = (const float*)d_in[6];
    const float* w_ih2   = (const float*)d_in[7];
    const float* w_hh2   = (const float*)d_in[8];
    const float* b_ih2   = (const float*)d_in[9];
    const float* b_hh2   = (const float*)d_in[10];
    const float* w_out   = (const float*)d_in[11];
    const float* b_out   = (const float*)d_in[12];
    float* out = (float*)d_out;

    float *pX1, *pWx2, *pW2, *pB1, *pB2, *pH12, *pC1, *pC2, *pPart, *pH2, *pLog;
    cudaGetSymbolAddress((void**)&pX1,  g_X1pre);
    cudaGetSymbolAddress((void**)&pWx2, g_Wx2);
    cudaGetSymbolAddress((void**)&pW2,  g_W2cat);
    cudaGetSymbolAddress((void**)&pB1,  g_bias1);
    cudaGetSymbolAddress((void**)&pB2,  g_bias2);
    cudaGetSymbolAddress((void**)&pH12, g_h12);
    cudaGetSymbolAddress((void**)&pC1,  g_c1);
    cudaGetSymbolAddress((void**)&pC2,  g_c2);
    cudaGetSymbolAddress((void**)&pPart, g_part);
    cudaGetSymbolAddress((void**)&pH2,  g_H2);
    cudaGetSymbolAddress((void**)&pLog, g_logits);

    init_kernel<<<1024, 256>>>(b_ih1, b_hh1, b_ih2, b_hh2, out);
    w2cat_kernel<<<8192, 256>>>(w_ih2, w_hh2);

    // X1pre[t,b,:] = feat[b,t,:] @ w_ih1^T + (b_ih1 + b_hh1)
    mma_gemm<<<dim3(16, 80, 1), 256>>>(feat, (size_t)FEATD, (size_t)TFRM * FEATD,
                                       w_ih1, FEATD, pB1, pX1, G4, FEATD, TFRM * BATCH);
    // Wx2[s,b,:] = caption[b,s,:] @ w_ih2[:, :512]^T   (no bias)
    mma_gemm<<<dim3(16, 29, 1), 256>>>(caption, (size_t)EDIM, (size_t)DECL * EDIM,
                                       w_ih2, 1024, nullptr, pWx2, G4, EDIM, DSTEPS * BATCH);
    argmax_kernel<<<DSTEPS * BATCH, 128>>>(oh);

    // encoder: 80 steps
    for (int t = 0; t < TFRM; t++) {
        mma_gemm<<<dim3(16, 1, NSPLIT), 256>>>(pH12, 0, 1024, w_hh1, EDIM, nullptr,
                                               pPart, G4, EDIM / NSPLIT, BATCH);
        cell_pointwise<<<256, 256>>>(pX1 + (size_t)t * BATCH * G4, nullptr, pC1, pH12, 0, nullptr);
        mma_gemm<<<dim3(16, 1, NSPLIT), 256>>>(pH12, 0, 1024, pW2, 1024, nullptr,
                                               pPart, G4, 1024 / NSPLIT, BATCH);
        cell_pointwise<<<256, 256>>>(nullptr, pB2, pC2, pH12, 512, nullptr);
    }
    // decoder: 29 steps
    for (int s = 0; s < DSTEPS; s++) {
        mma_gemm<<<dim3(16, 1, NSPLIT), 256>>>(pH12, 0, 1024, w_hh1, EDIM, nullptr,
                                               pPart, G4, EDIM / NSPLIT, BATCH);
        cell_pointwise<<<256, 256>>>(nullptr, pB1, pC1, pH12, 0, nullptr);
        mma_gemm<<<dim3(16, 1, NSPLIT), 256>>>(pH12, 0, 1024, pW2, 1024, nullptr,
                                               pPart, G4, 1024 / NSPLIT, BATCH);
        cell_pointwise<<<256, 256>>>(pWx2 + (size_t)s * BATCH * G4, pB2, pC2, pH12, 512,
                                     pH2 + (size_t)s * BATCH * EDIM);
    }

    // logits = H2 @ w_out^T + b_out  -> [3712, 6000]
    mma_gemm<<<dim3(47, 29, 1), 256>>>(pH2, (size_t)BATCH * EDIM, (size_t)EDIM,
                                       w_out, EDIM, b_out, pLog, VOC, EDIM, DSTEPS * BATCH);
    loss_kernel<<<DSTEPS * BATCH, 256>>>();
    final_reduce<<<1, 256>>>(out);
}